// round 1
// baseline (speedup 1.0000x reference)
#include <cuda_runtime.h>
#include <math.h>
#include <stdint.h>

#define L   401
#define B   256
#define BC  32           // batches per block chunk
#define LL  (L * L)

// ---------------- device globals (no allocations allowed) ----------------
__device__ double g_bins[L];
__device__ double g_sc[4];   // 0: ctcf_num, 1: within_num, 2: nc_sum, 3: cnt_within
__device__ unsigned char g_attrA[B * L];   // bit0=a(o!=0), bit1=f(o==1),  bit2=comp
__device__ unsigned char g_attrB[B * L];   // bit0=a,       bit1=r(o==-1), bit2=comp

// ---------------- kernel 0: zero accumulators ----------------
__global__ void zero_kernel() {
    int t = threadIdx.x;
    for (int s = t; s < L; s += blockDim.x) g_bins[s] = 0.0;
    if (t < 4) g_sc[t] = 0.0;
}

// ---------------- kernel 1: per-(b,pos) attributes + analytic counts ----------------
__global__ void prep_kernel(const int* __restrict__ ctcf,
                            const float* __restrict__ logits) {
    const int b = blockIdx.x;
    const int p = threadIdx.x;

    __shared__ int cnt[5];                 // A, F, R, n1, adjEq
    __shared__ unsigned char compsh[L];
    if (p < 5) cnt[p] = 0;
    __syncthreads();

    int a = 0, f = 0, r = 0, c = 0;
    if (p < L) {
        int o = ctcf[b * L + p];
        a = (o != 0);
        f = (o == 1);
        r = (o == -1);
        float l0 = logits[(b * L + p) * 2 + 0];
        float l1 = logits[(b * L + p) * 2 + 1];
        c = (l1 > l0);                     // argmax ties -> 0, matches jnp.argmax
        g_attrA[b * L + p] = (unsigned char)(a | (f << 1) | (c << 2));
        g_attrB[b * L + p] = (unsigned char)(a | (r << 1) | (c << 2));
        compsh[p] = (unsigned char)c;
    }
    __syncthreads();

    int adj = 0;
    if (p < L - 1) adj = (compsh[p] == compsh[p + 1]);

    atomicAdd(&cnt[0], a);
    atomicAdd(&cnt[1], f);
    atomicAdd(&cnt[2], r);
    atomicAdd(&cnt[3], c);
    atomicAdd(&cnt[4], adj);
    __syncthreads();

    if (p == 0) {
        double A = cnt[0], F = cnt[1], R = cnt[2];
        double n1 = cnt[3];
        double n0 = (double)L - n1;
        double nc = A * A - F * R;                         // sum non_conv (counts)
        double cw = n0 * n0 + n1 * n1 - (double)L - 2.0 * (double)cnt[4]; // same & d>=2
        atomicAdd(&g_sc[2], nc);
        atomicAdd(&g_sc[3], cw);
    }
}

// ---------------- kernel 2: the big streaming pass ----------------
// block = (batch-chunk, row i); thread tid owns j0=tid and (if <L) j1=tid+256.
__global__ __launch_bounds__(256) void main_kernel(const float* __restrict__ cm) {
    const int i   = blockIdx.y;
    const int b0  = blockIdx.x * BC;
    const int tid = threadIdx.x;

    __shared__ uint32_t shB32[(L * BC) / 4];   // attrB transposed: [j][bb], 12832 B
    __shared__ uint32_t shA32[BC / 4];
    unsigned char* shB = (unsigned char*)shB32;
    unsigned char* shA = (unsigned char*)shA32;

    // stage attrB (coalesced global read, strided shared write — one-time)
    for (int bb = 0; bb < BC; ++bb)
        for (int j = tid; j < L; j += 256)
            shB[j * BC + bb] = g_attrB[(b0 + bb) * L + j];
    if (tid < BC) shA[tid] = g_attrA[(b0 + tid) * L + i];
    __syncthreads();

    uint32_t aiw[BC / 4];
#pragma unroll
    for (int k = 0; k < BC / 4; ++k) aiw[k] = shA32[k];

    const int  j0   = tid;
    const int  j1   = tid + 256;
    const bool has1 = (j1 < L);
    const int  d0   = abs(i - j0);
    const int  d1   = has1 ? abs(i - j1) : 0;
    const bool m0   = (d0 >= 2);
    const bool m1   = has1 && (d1 >= 2);

    float s0 = 0.f, s1 = 0.f, ctcf = 0.f, win = 0.f;
    const float* base = cm + (size_t)b0 * LL + (size_t)i * L;

#pragma unroll
    for (int g = 0; g < BC / 4; ++g) {
        uint32_t ai4 = aiw[g];
        uint32_t aj0 = shB32[j0 * (BC / 4) + g];
        uint32_t aj1 = has1 ? shB32[j1 * (BC / 4) + g] : 0u;

        float v0[4], v1[4];
#pragma unroll
        for (int k = 0; k < 4; ++k) {
            const float* p = base + (size_t)(g * 4 + k) * LL;
            v0[k] = __ldg(p + j0);
            v1[k] = has1 ? __ldg(p + j1) : 0.f;
        }

        uint32_t an0 = ai4 & aj0, xo0 = ai4 ^ aj0;
        uint32_t an1 = ai4 & aj1, xo1 = ai4 ^ aj1;

#pragma unroll
        for (int k = 0; k < 4; ++k) {
            {
                float v = v0[k];
                s0 += v;
                unsigned an = (an0 >> (8 * k)) & 0xffu;
                unsigned xo = (xo0 >> (8 * k)) & 0xffu;
                if ((an & 3u) == 1u) ctcf += fmaxf(v, 0.f);   // a_i&a_j & !(f_i&r_j)
                if (m0 && ((xo & 4u) == 0u)) win += v;        // same-compartment, d>=2
            }
            if (has1) {
                float v = v1[k];
                s1 += v;
                unsigned an = (an1 >> (8 * k)) & 0xffu;
                unsigned xo = (xo1 >> (8 * k)) & 0xffu;
                if ((an & 3u) == 1u) ctcf += fmaxf(v, 0.f);
                if (m1 && ((xo & 4u) == 0u)) win += v;
            }
        }
    }

    // one double atomic per (thread, slot) into its distance bin
    atomicAdd(&g_bins[d0], (double)s0);
    if (has1) atomicAdd(&g_bins[d1], (double)s1);

    // block-reduce the two scalar accumulators -> one double atomic each
    for (int o = 16; o; o >>= 1) {
        ctcf += __shfl_down_sync(0xffffffffu, ctcf, o);
        win  += __shfl_down_sync(0xffffffffu, win,  o);
    }
    __shared__ float red[2][8];
    int wid = tid >> 5, lane = tid & 31;
    if (lane == 0) { red[0][wid] = ctcf; red[1][wid] = win; }
    __syncthreads();
    if (tid == 0) {
        float c = 0.f, w = 0.f;
#pragma unroll
        for (int k = 0; k < 8; ++k) { c += red[0][k]; w += red[1][k]; }
        atomicAdd(&g_sc[0], (double)c);
        atomicAdd(&g_sc[1], (double)w);
    }
}

// ---------------- kernel 3: finalize ----------------
__device__ __forceinline__ double blockReduceD(double v, double* scratch) {
    for (int o = 16; o; o >>= 1) v += __shfl_down_sync(0xffffffffu, v, o);
    int wid = threadIdx.x >> 5, lane = threadIdx.x & 31;
    __syncthreads();
    if (lane == 0) scratch[wid] = v;
    __syncthreads();
    if (threadIdx.x == 0) {
        double r = 0.0;
        for (int k = 0; k < 16; ++k) r += scratch[k];
        scratch[16] = r;
    }
    __syncthreads();
    return scratch[16];
}

__global__ void final_kernel(float* __restrict__ out) {
    const int t = threadIdx.x;     // 512 threads, bins handled by t < L
    __shared__ double scratch[17];

    double w = 0.0, ld = 0.0, lp = 0.0, maskedv = 0.0;
    if (t < L) {
        double cntp = (t == 0) ? (double)L : 2.0 * (double)(L - t);
        double mc = g_bins[t] / (cntp * (double)B);
        bool valid = (t >= 2) && isfinite(mc) && (mc > 0.0);
        w  = valid ? 1.0 : 0.0;
        ld = log(fmax((double)t, 1.0));
        lp = log((valid ? mc : 1.0) + 1e-6);
        if (t >= 2) maskedv = g_bins[t];
    }

    double n   = blockReduceD(w, scratch);
    double sx  = blockReduceD(w * ld, scratch);
    double sy  = blockReduceD(w * lp, scratch);
    double msk = blockReduceD(maskedv, scratch);
    double ns  = fmax(n, 1.0);
    double xm  = sx / ns, ym = sy / ns;
    double num = blockReduceD(w * (ld - xm) * (lp - ym), scratch);
    double den = blockReduceD(w * (ld - xm) * (ld - xm), scratch);

    if (t == 0) {
        // distance decay
        double slope = num / (den + 1e-8);
        double dist  = (n >= 5.0) ? (slope + 0.85) * (slope + 0.85) : 0.0;
        // ctcf
        double ncs   = g_sc[2];
        double hinge = g_sc[0] / (ncs + 1e-6);
        double ctcfl = (ncs < 1.0) ? 0.0 : hinge;
        // compartment
        double cw      = g_sc[3];
        double cb      = 159600.0 * (double)B - cw;   // (L-1)(L-2) masked pairs per batch
        double within  = g_sc[1] / fmax(cw, 1.0);
        double between = (msk - g_sc[1]) / fmax(cb, 1.0);
        double ratio   = within / (fabs(between) + 1e-6);
        double compl_  = fmax(1.5 - ratio, 0.0);

        out[0] = (float)dist;
        out[1] = (float)ctcfl;
        out[2] = (float)compl_;
        out[3] = (float)(dist + 0.5 * ctcfl + 0.5 * compl_);
    }
}

// ---------------- launch ----------------
extern "C" void kernel_launch(void* const* d_in, const int* in_sizes, int n_in,
                              void* d_out, int out_size) {
    const float* cm     = (const float*)d_in[0];   // (B, L, L) f32
    const float* logits = (const float*)d_in[1];   // (B, L, 2) f32
    const int*   ctcf   = (const int*)d_in[2];     // (B, L)    i32
    float*       out    = (float*)d_out;           // 4 f32

    zero_kernel<<<1, 512>>>();
    prep_kernel<<<B, 512>>>(ctcf, logits);
    dim3 grid(B / BC, L);
    main_kernel<<<grid, 256>>>(cm);
    final_kernel<<<1, 512>>>(out);
}

// round 2
// speedup vs baseline: 2.1481x; 2.1481x over previous
#include <cuda_runtime.h>
#include <math.h>
#include <stdint.h>

#define L   401
#define B   256
#define LL  (L * L)
#define CH  32                    // batches per chunk in main kernel

// ---------------- device globals ----------------
__device__ double g_bins[L * 16];          // padded: bin d at [d*16] -> 1 bin per 128B line
__device__ double g_sc[4];                 // 0: ctcf_num, 1: within_num, 2: nc_sum, 3: cnt_within
__device__ unsigned char g_attrAT[L * B];  // [pos][batch]: bit0=a, bit1=f, bit2=comp
__device__ unsigned char g_attrBT[L * B];  // [pos][batch]: bit0=a, bit1=r, bit2=comp

// ---------------- kernel 0: zero accumulators ----------------
__global__ void zero_kernel() {
    int t = threadIdx.x;
    for (int s = t; s < L * 16; s += blockDim.x) g_bins[s] = 0.0;
    if (t < 4) g_sc[t] = 0.0;
}

// ---------------- kernel 1: attributes (transposed) + analytic counts ----------------
__global__ void prep_kernel(const int* __restrict__ ctcf,
                            const float* __restrict__ logits) {
    const int b = blockIdx.x;
    const int p = threadIdx.x;

    __shared__ int cnt[5];                 // A, F, R, n1, adjEq
    __shared__ unsigned char compsh[L];
    if (p < 5) cnt[p] = 0;
    __syncthreads();

    int a = 0, f = 0, r = 0, c = 0;
    if (p < L) {
        int o = ctcf[b * L + p];
        a = (o != 0);
        f = (o == 1);
        r = (o == -1);
        float l0 = logits[(b * L + p) * 2 + 0];
        float l1 = logits[(b * L + p) * 2 + 1];
        c = (l1 > l0);                     // argmax, ties -> 0
        g_attrAT[p * B + b] = (unsigned char)(a | (f << 1) | (c << 2));
        g_attrBT[p * B + b] = (unsigned char)(a | (r << 1) | (c << 2));
        compsh[p] = (unsigned char)c;
    }
    __syncthreads();

    int adj = 0;
    if (p < L - 1) adj = (compsh[p] == compsh[p + 1]);

    atomicAdd(&cnt[0], a);
    atomicAdd(&cnt[1], f);
    atomicAdd(&cnt[2], r);
    atomicAdd(&cnt[3], c);
    atomicAdd(&cnt[4], adj);
    __syncthreads();

    if (p == 0) {
        double A = cnt[0], F = cnt[1], R = cnt[2];
        double n1 = cnt[3];
        double n0 = (double)L - n1;
        double nc = A * A - F * R;                                        // non_conv count
        double cw = n0 * n0 + n1 * n1 - (double)L - 2.0 * (double)cnt[4]; // same & d>=2
        atomicAdd(&g_sc[2], nc);
        atomicAdd(&g_sc[3], cw);
    }
}

// ---------------- kernel 2: streaming pass ----------------
// block = row i (grid = 401). Each block covers ALL 256 batches.
// thread tid owns j0 = tid and (if tid < 145) j1 = tid + 256.
__global__ __launch_bounds__(256) void main_kernel(const float* __restrict__ cm) {
    const int i   = blockIdx.x;
    const int tid = threadIdx.x;

    const int  j0   = tid;
    const int  j1   = tid + 256;
    const bool has1 = (j1 < L);
    const int  d0   = abs(i - j0);
    const int  d1   = has1 ? abs(i - j1) : 0;
    const uint32_t mc0 = (d0 >= 2) ? 0x04040404u : 0u;
    const uint32_t mc1 = (has1 && d1 >= 2) ? 0x04040404u : 0u;

    const uint32_t* aT  = (const uint32_t*)g_attrAT + i * (B / 4);
    const uint32_t* bT0 = (const uint32_t*)g_attrBT + j0 * (B / 4);
    const uint32_t* bT1 = (const uint32_t*)g_attrBT + (has1 ? j1 : j0) * (B / 4);

    double bs0 = 0.0, bs1 = 0.0;
    float  ct = 0.f, wn = 0.f;
    const float* rowbase = cm + (size_t)i * L;

    for (int c = 0; c < B / CH; ++c) {
        float s0 = 0.f, s1 = 0.f;
#pragma unroll
        for (int g = 0; g < CH / 4; ++g) {
            const int w = c * (CH / 4) + g;
            uint32_t ai   = __ldg(aT + w);
            uint32_t aj0w = __ldg(bT0 + w);
            uint32_t aj1w = __ldg(bT1 + w);

            uint32_t an0 = ai & aj0w;
            uint32_t t10 = an0 & ~(an0 >> 1) & 0x01010101u;   // a_i&a_j & !(f_i&r_j)
            uint32_t t20 = ~(ai ^ aj0w) & mc0;                // same compartment & d>=2
            uint32_t an1 = ai & aj1w;
            uint32_t t11 = an1 & ~(an1 >> 1) & 0x01010101u;
            uint32_t t21 = ~(ai ^ aj1w) & mc1;

            float v0[4], v1[4];
            const float* p = rowbase + (size_t)(c * CH + g * 4) * LL;
#pragma unroll
            for (int k = 0; k < 4; ++k) {
                v0[k] = __ldg(p + (size_t)k * LL + j0);
                v1[k] = has1 ? __ldg(p + (size_t)k * LL + j1) : 0.f;
            }
#pragma unroll
            for (int k = 0; k < 4; ++k) {
                {
                    float v = v0[k];
                    s0 += v;
                    if (t10 & (1u << (8 * k))) ct += fmaxf(v, 0.f);
                    if (t20 & (4u << (8 * k))) wn += v;
                }
                if (has1) {
                    float u = v1[k];
                    s1 += u;
                    if (t11 & (1u << (8 * k))) ct += fmaxf(u, 0.f);
                    if (t21 & (4u << (8 * k))) wn += u;
                }
            }
        }
        bs0 += (double)s0;
        bs1 += (double)s1;
    }

    // one double atomic per thread-slot (161k total, 1 bin per 128B line)
    atomicAdd(&g_bins[d0 * 16], bs0);
    if (has1) atomicAdd(&g_bins[d1 * 16], bs1);

    // block-reduce the two scalar accumulators -> one double atomic each
    for (int o = 16; o; o >>= 1) {
        ct += __shfl_down_sync(0xffffffffu, ct, o);
        wn += __shfl_down_sync(0xffffffffu, wn, o);
    }
    __shared__ float red[2][8];
    int wid = tid >> 5, lane = tid & 31;
    if (lane == 0) { red[0][wid] = ct; red[1][wid] = wn; }
    __syncthreads();
    if (tid == 0) {
        float c = 0.f, w = 0.f;
#pragma unroll
        for (int k = 0; k < 8; ++k) { c += red[0][k]; w += red[1][k]; }
        atomicAdd(&g_sc[0], (double)c);
        atomicAdd(&g_sc[1], (double)w);
    }
}

// ---------------- kernel 3: finalize (f32 regression, matches reference dtype) ----------------
__device__ __forceinline__ float blockReduceF(float v, float* scratch) {
    for (int o = 16; o; o >>= 1) v += __shfl_down_sync(0xffffffffu, v, o);
    int wid = threadIdx.x >> 5, lane = threadIdx.x & 31;
    __syncthreads();
    if (lane == 0) scratch[wid] = v;
    __syncthreads();
    if (threadIdx.x == 0) {
        float r = 0.f;
        for (int k = 0; k < 16; ++k) r += scratch[k];
        scratch[16] = r;
    }
    __syncthreads();
    return scratch[16];
}

__global__ void final_kernel(float* __restrict__ out) {
    const int t = threadIdx.x;     // 512 threads
    __shared__ float scratchf[17];
    __shared__ double msk_sh[17];

    float w = 0.f, ld = 0.f, lp = 0.f;
    double maskedv = 0.0;
    if (t < L) {
        double cntp = (t == 0) ? (double)L : 2.0 * (double)(L - t);
        double mc = g_bins[t * 16] / (cntp * (double)B);
        bool valid = (t >= 2) && isfinite(mc) && (mc > 0.0);
        w  = valid ? 1.f : 0.f;
        ld = logf(fmaxf((float)t, 1.0f));
        lp = logf((float)((valid ? mc : 1.0) + 1e-6));
        if (t >= 2) maskedv = g_bins[t * 16];
    }

    // double reduce for masked bin total
    {
        double v = maskedv;
        for (int o = 16; o; o >>= 1) v += __shfl_down_sync(0xffffffffu, v, o);
        int wid = threadIdx.x >> 5, lane = threadIdx.x & 31;
        if (lane == 0) msk_sh[wid] = v;
        __syncthreads();
        if (threadIdx.x == 0) {
            double r = 0.0;
            for (int k = 0; k < 16; ++k) r += msk_sh[k];
            msk_sh[16] = r;
        }
        __syncthreads();
    }
    double msk = msk_sh[16];

    float n   = blockReduceF(w, scratchf);
    float sx  = blockReduceF(w * ld, scratchf);
    float sy  = blockReduceF(w * lp, scratchf);
    float ns  = fmaxf(n, 1.0f);
    float xm  = sx / ns, ym = sy / ns;
    float num = blockReduceF(w * (ld - xm) * (lp - ym), scratchf);
    float den = blockReduceF(w * (ld - xm) * (ld - xm), scratchf);

    if (t == 0) {
        // distance decay
        double slope = (double)num / ((double)den + 1e-8);
        double dist  = (n >= 5.0f) ? (slope + 0.85) * (slope + 0.85) : 0.0;
        // ctcf
        double ncs   = g_sc[2];
        double hinge = g_sc[0] / (ncs + 1e-6);
        double ctcfl = (ncs < 1.0) ? 0.0 : hinge;
        // compartment
        double cw      = g_sc[3];
        double cb      = 159600.0 * (double)B - cw;   // (L-1)(L-2) masked pairs per batch
        double within  = g_sc[1] / fmax(cw, 1.0);
        double between = (msk - g_sc[1]) / fmax(cb, 1.0);
        double ratio   = within / (fabs(between) + 1e-6);
        double compl_  = fmax(1.5 - ratio, 0.0);

        out[0] = (float)dist;
        out[1] = (float)ctcfl;
        out[2] = (float)compl_;
        out[3] = (float)(dist + 0.5 * ctcfl + 0.5 * compl_);
    }
}

// ---------------- launch ----------------
extern "C" void kernel_launch(void* const* d_in, const int* in_sizes, int n_in,
                              void* d_out, int out_size) {
    const float* cm     = (const float*)d_in[0];   // (B, L, L) f32
    const float* logits = (const float*)d_in[1];   // (B, L, 2) f32
    const int*   ctcf   = (const int*)d_in[2];     // (B, L)    i32
    float*       out    = (float*)d_out;           // 4 f32

    zero_kernel<<<1, 512>>>();
    prep_kernel<<<B, 512>>>(ctcf, logits);
    main_kernel<<<L, 256>>>(cm);
    final_kernel<<<1, 512>>>(out);
}

// round 4
// speedup vs baseline: 2.5369x; 1.1810x over previous
#include <cuda_runtime.h>
#include <math.h>
#include <stdint.h>

#define L   401
#define B   256
#define LL  (L * L)
#define NCHUNK 4                 // batch chunks in main grid
#define BCHUNK (B / NCHUNK)      // 64 batches per main block
#define PW  (3 * L)              // words per batch-word slab: [plane][j]

// ---------------- device globals ----------------
__device__ float    g_bins[L];
__device__ double   g_sc[4];               // 0: ctcf_num, 1: within_num, 2: nc_sum, 3: cnt_within
__device__ uint32_t g_planes[8 * PW];      // [batch_word w][plane f/r/c][j] bit b%32

// ---------------- kernel 1a: analytic per-batch counts ----------------
__global__ void prep_counts(const int* __restrict__ ctcf,
                            const float* __restrict__ logits) {
    const int b = blockIdx.x;
    const int p = threadIdx.x;

    __shared__ int cnt[5];                 // A, F, R, n1, adjEq
    __shared__ unsigned char compsh[L];
    if (p < 5) cnt[p] = 0;
    __syncthreads();

    int a = 0, f = 0, r = 0, c = 0;
    if (p < L) {
        int o = ctcf[b * L + p];
        a = (o != 0);
        f = (o == 1);
        r = (o == -1);
        float l0 = logits[(b * L + p) * 2 + 0];
        float l1 = logits[(b * L + p) * 2 + 1];
        c = (l1 > l0);                     // argmax, ties -> 0
        compsh[p] = (unsigned char)c;
    }
    __syncthreads();

    int adj = 0;
    if (p < L - 1) adj = (compsh[p] == compsh[p + 1]);

    atomicAdd(&cnt[0], a);
    atomicAdd(&cnt[1], f);
    atomicAdd(&cnt[2], r);
    atomicAdd(&cnt[3], c);
    atomicAdd(&cnt[4], adj);
    __syncthreads();

    if (p == 0) {
        double A = cnt[0], F = cnt[1], R = cnt[2];
        double n1 = cnt[3];
        double n0 = (double)L - n1;
        double nc = A * A - F * R;                                        // non_conv count
        double cw = n0 * n0 + n1 * n1 - (double)L - 2.0 * (double)cnt[4]; // same & d>=2
        atomicAdd(&g_sc[2], nc);
        atomicAdd(&g_sc[3], cw);
    }
}

// ---------------- kernel 1b: bit-planes via ballot ----------------
// block = position p, thread = batch b. Word w = b/32, bit = b%32.
__global__ __launch_bounds__(256) void prep_planes(const int* __restrict__ ctcf,
                                                   const float* __restrict__ logits) {
    const int p = blockIdx.x;
    const int b = threadIdx.x;

    int o = ctcf[b * L + p];
    int f = (o == 1);
    int r = (o == -1);
    float l0 = logits[(b * L + p) * 2 + 0];
    float l1 = logits[(b * L + p) * 2 + 1];
    int c = (l1 > l0);

    uint32_t bf = __ballot_sync(0xffffffffu, f);
    uint32_t br = __ballot_sync(0xffffffffu, r);
    uint32_t bc = __ballot_sync(0xffffffffu, c);

    if ((b & 31) == 0) {
        int w = b >> 5;
        g_planes[w * PW + 0 * L + p] = bf;
        g_planes[w * PW + 1 * L + p] = br;
        g_planes[w * PW + 2 * L + p] = bc;
    }
}

// ---------------- kernel 2: streaming pass ----------------
// block = (batch chunk, row i); thread tid owns j0 = tid and (if <145) j1 = tid+256.
__global__ __launch_bounds__(256) void main_kernel(const float* __restrict__ cm) {
    const int i   = blockIdx.y;
    const int tid = threadIdx.x;
    const int w0  = blockIdx.x * 2;        // first batch-word of this chunk

    __shared__ uint32_t sh[2 * PW];        // 9.6 KB: the 2 batch-words this block needs
    for (int idx = tid; idx < 2 * PW; idx += 256)
        sh[idx] = g_planes[w0 * PW + idx];
    __syncthreads();

    const int  j0   = tid;
    const int  j1   = tid + 256;
    const bool has1 = (j1 < L);
    const int  d0   = abs(i - j0);
    const int  d1   = has1 ? abs(i - j1) : 0;

    float s0 = 0.f, s1 = 0.f, ct = 0.f, wn = 0.f;
    const float* base = cm + (size_t)(blockIdx.x * BCHUNK) * LL + (size_t)i * L;

#pragma unroll
    for (int h = 0; h < 2; ++h) {
        const uint32_t* s = sh + h * PW;
        uint32_t fi = s[i], ri = s[L + i], ci = s[2 * L + i];
        uint32_t ai = fi | ri;

        uint32_t fj = s[j0], rj = s[L + j0], cj = s[2 * L + j0];
        uint32_t t10 = ai & (fj | rj) & ~(fi & rj);      // pair has ctcf & not convergent
        uint32_t t20 = (d0 >= 2) ? ~(ci ^ cj) : 0u;      // same compartment & d>=2

        uint32_t t11 = 0u, t21 = 0u;
        if (has1) {
            uint32_t fk = s[j1], rk = s[L + j1], ck = s[2 * L + j1];
            t11 = ai & (fk | rk) & ~(fi & rk);
            t21 = (d1 >= 2) ? ~(ci ^ ck) : 0u;
        }

        const float* pb = base + (size_t)h * 32 * LL;
#pragma unroll
        for (int k = 0; k < 32; ++k) {
            float v = __ldg(pb + (size_t)k * LL + j0);
            s0 += v;
            if ((t10 >> k) & 1u) ct += fmaxf(v, 0.f);
            if ((t20 >> k) & 1u) wn += v;
            if (has1) {
                float u = __ldg(pb + (size_t)k * LL + j1);
                s1 += u;
                if ((t11 >> k) & 1u) ct += fmaxf(u, 0.f);
                if ((t21 >> k) & 1u) wn += u;
            }
        }
    }

    // one float atomic per thread-slot into its distance bin
    atomicAdd(&g_bins[d0], s0);
    if (has1) atomicAdd(&g_bins[d1], s1);

    // block-reduce scalars -> one double atomic each
    for (int o = 16; o; o >>= 1) {
        ct += __shfl_down_sync(0xffffffffu, ct, o);
        wn += __shfl_down_sync(0xffffffffu, wn, o);
    }
    __shared__ float red[2][8];
    int wid = tid >> 5, lane = tid & 31;
    if (lane == 0) { red[0][wid] = ct; red[1][wid] = wn; }
    __syncthreads();
    if (tid == 0) {
        float c = 0.f, w = 0.f;
#pragma unroll
        for (int k = 0; k < 8; ++k) { c += red[0][k]; w += red[1][k]; }
        atomicAdd(&g_sc[0], (double)c);
        atomicAdd(&g_sc[1], (double)w);
    }
}

// ---------------- kernel 3: finalize (f32) + reset state for next replay ----------------
__device__ __forceinline__ float blockReduceF(float v, float* scratch) {
    for (int o = 16; o; o >>= 1) v += __shfl_down_sync(0xffffffffu, v, o);
    int wid = threadIdx.x >> 5, lane = threadIdx.x & 31;
    __syncthreads();
    if (lane == 0) scratch[wid] = v;
    __syncthreads();
    if (threadIdx.x == 0) {
        float r = 0.f;
        for (int k = 0; k < 16; ++k) r += scratch[k];
        scratch[16] = r;
    }
    __syncthreads();
    return scratch[16];
}

__global__ void final_kernel(float* __restrict__ out) {
    const int t = threadIdx.x;     // 512 threads
    __shared__ float scratchf[17];

    float w = 0.f, ld = 0.f, lp = 0.f, maskedv = 0.f;
    if (t < L) {
        float binv = g_bins[t];
        float cntp = (t == 0) ? (float)L : 2.0f * (float)(L - t);
        float mc = binv / (cntp * (float)B);
        bool valid = (t >= 2) && isfinite(mc) && (mc > 0.0f);
        w  = valid ? 1.f : 0.f;
        ld = logf(fmaxf((float)t, 1.0f));
        lp = logf((valid ? mc : 1.0f) + 1e-6f);
        if (t >= 2) maskedv = binv;
    }

    float msk = blockReduceF(maskedv, scratchf);
    float n   = blockReduceF(w, scratchf);
    float sx  = blockReduceF(w * ld, scratchf);
    float sy  = blockReduceF(w * lp, scratchf);
    float ns  = fmaxf(n, 1.0f);
    float xm  = sx / ns, ym = sy / ns;
    float num = blockReduceF(w * (ld - xm) * (lp - ym), scratchf);
    float den = blockReduceF(w * (ld - xm) * (ld - xm), scratchf);

    if (t == 0) {
        // distance decay
        double slope = (double)num / ((double)den + 1e-8);
        double dist  = (n >= 5.0f) ? (slope + 0.85) * (slope + 0.85) : 0.0;
        // ctcf
        double ncs   = g_sc[2];
        double hinge = g_sc[0] / (ncs + 1e-6);
        double ctcfl = (ncs < 1.0) ? 0.0 : hinge;
        // compartment
        double cw      = g_sc[3];
        double cb      = 159600.0 * (double)B - cw;   // (L-1)(L-2) masked pairs per batch
        double within  = g_sc[1] / fmax(cw, 1.0);
        double between = ((double)msk - g_sc[1]) / fmax(cb, 1.0);
        double ratio   = within / (fabs(between) + 1e-6);
        double compl_  = fmax(1.5 - ratio, 0.0);

        out[0] = (float)dist;
        out[1] = (float)ctcfl;
        out[2] = (float)compl_;
        out[3] = (float)(dist + 0.5 * ctcfl + 0.5 * compl_);
    }

    // reset accumulators for the next graph replay (all reads above are done)
    __syncthreads();
    if (t < L) g_bins[t] = 0.f;
    if (t < 4) g_sc[t] = 0.0;
}

// ---------------- launch ----------------
extern "C" void kernel_launch(void* const* d_in, const int* in_sizes, int n_in,
                              void* d_out, int out_size) {
    const float* cm     = (const float*)d_in[0];   // (B, L, L) f32
    const float* logits = (const float*)d_in[1];   // (B, L, 2) f32
    const int*   ctcf   = (const int*)d_in[2];     // (B, L)    i32
    float*       out    = (float*)d_out;           // 4 f32

    prep_counts<<<B, 512>>>(ctcf, logits);
    prep_planes<<<L, 256>>>(ctcf, logits);
    dim3 grid(NCHUNK, L);
    main_kernel<<<grid, 256>>>(cm);
    final_kernel<<<1, 512>>>(out);
}

// round 5
// speedup vs baseline: 3.1986x; 1.2608x over previous
#include <cuda_runtime.h>
#include <math.h>
#include <stdint.h>

#define L   401
#define B   256
#define LL  (L * L)
#define NCHUNK 4                 // batch chunks in main grid
#define BCHUNK (B / NCHUNK)      // 64 batches per main block
#define PW  (3 * L)              // words per batch-word slab: [plane][j]
#define NBLK (NCHUNK * L)        // 1604 main blocks

// ---------------- device globals ----------------
__device__ float    g_bins[L * 32];        // one bin per 128B line: bin d at [d*32]
__device__ float    g_scf[2 * 32];         // [0]=ctcf_num, [32]=within_num (padded lines)
__device__ int      g_sci[2 * 32];         // [0]=nc_sum,   [32]=cnt_within (exact ints)
__device__ uint32_t g_planes[8 * PW];      // [batch_word][plane f/r/c][j], bit = b%32
__device__ unsigned int g_done;

// ---------------- kernel 1: merged prep (planes + analytic counts) ----------------
__global__ __launch_bounds__(512) void prep_kernel(const int* __restrict__ ctcf,
                                                   const float* __restrict__ logits) {
    const int blk = blockIdx.x;
    const int t   = threadIdx.x;

    if (blk < L) {
        // ----- bit-planes: position p = blk, batch b = t (warps 0-7 active, uniform) -----
        if (t < B) {
            const int p = blk, b = t;
            int o = ctcf[b * L + p];
            float l0 = logits[(b * L + p) * 2 + 0];
            float l1 = logits[(b * L + p) * 2 + 1];
            uint32_t bf = __ballot_sync(0xffffffffu, o == 1);
            uint32_t br = __ballot_sync(0xffffffffu, o == -1);
            uint32_t bc = __ballot_sync(0xffffffffu, l1 > l0);
            if ((b & 31) == 0) {
                int w = b >> 5;
                g_planes[w * PW + 0 * L + p] = bf;
                g_planes[w * PW + 1 * L + p] = br;
                g_planes[w * PW + 2 * L + p] = bc;
            }
        }
    } else {
        // ----- analytic per-batch counts: batch b = blk - L, position p = t -----
        const int b = blk - L;
        const int p = t;
        __shared__ int cnt[5];                 // A, F, R, n1, adjEq
        __shared__ unsigned char compsh[L];
        if (p < 5) cnt[p] = 0;
        __syncthreads();

        int a = 0, f = 0, r = 0, c = 0;
        if (p < L) {
            int o = ctcf[b * L + p];
            a = (o != 0);
            f = (o == 1);
            r = (o == -1);
            float l0 = logits[(b * L + p) * 2 + 0];
            float l1 = logits[(b * L + p) * 2 + 1];
            c = (l1 > l0);                     // argmax, ties -> 0
            compsh[p] = (unsigned char)c;
        }
        __syncthreads();

        int adj = 0;
        if (p < L - 1) adj = (compsh[p] == compsh[p + 1]);

        atomicAdd(&cnt[0], a);
        atomicAdd(&cnt[1], f);
        atomicAdd(&cnt[2], r);
        atomicAdd(&cnt[3], c);
        atomicAdd(&cnt[4], adj);
        __syncthreads();

        if (p == 0) {
            int A = cnt[0], F = cnt[1], R = cnt[2], n1 = cnt[3];
            int n0 = L - n1;
            int nc = A * A - F * R;                            // non_conv count (exact)
            int cw = n0 * n0 + n1 * n1 - L - 2 * cnt[4];       // same & d>=2 (exact)
            atomicAdd(&g_sci[0],  nc);
            atomicAdd(&g_sci[32], cw);
        }
    }
}

// ---------------- kernel 2: streaming pass + last-block finalize ----------------
__global__ __launch_bounds__(256) void main_kernel(const float* __restrict__ cm,
                                                   float* __restrict__ out) {
    const int i   = blockIdx.y;
    const int tid = threadIdx.x;
    const int w0  = blockIdx.x * 2;        // first batch-word of this chunk

    __shared__ uint32_t sh[2 * PW];        // 9.6 KB: the 2 batch-words this block needs
    for (int idx = tid; idx < 2 * PW; idx += 256)
        sh[idx] = g_planes[w0 * PW + idx];
    __syncthreads();

    const int  j0   = tid;
    const int  j1   = tid + 256;
    const bool has1 = (j1 < L);
    const int  d0   = abs(i - j0);
    const int  d1   = has1 ? abs(i - j1) : 0;

    float s0 = 0.f, s1 = 0.f, ct = 0.f, wn = 0.f;
    const float* base = cm + (size_t)(blockIdx.x * BCHUNK) * LL + (size_t)i * L;

#pragma unroll
    for (int h = 0; h < 2; ++h) {
        const uint32_t* s = sh + h * PW;
        uint32_t fi = s[i], ri = s[L + i], ci = s[2 * L + i];
        uint32_t ai = fi | ri;

        uint32_t fj = s[j0], rj = s[L + j0], cj = s[2 * L + j0];
        uint32_t t10 = ai & (fj | rj) & ~(fi & rj);      // pair has ctcf & not convergent
        uint32_t t20 = (d0 >= 2) ? ~(ci ^ cj) : 0u;      // same compartment & d>=2

        uint32_t t11 = 0u, t21 = 0u;
        if (has1) {
            uint32_t fk = s[j1], rk = s[L + j1], ck = s[2 * L + j1];
            t11 = ai & (fk | rk) & ~(fi & rk);
            t21 = (d1 >= 2) ? ~(ci ^ ck) : 0u;
        }

        const float* pb = base + (size_t)h * 32 * LL;
#pragma unroll
        for (int k = 0; k < 32; ++k) {
            float v = __ldg(pb + (size_t)k * LL + j0);
            s0 += v;
            if ((t10 >> k) & 1u) ct += fmaxf(v, 0.f);
            if ((t20 >> k) & 1u) wn += v;
            if (has1) {
                float u = __ldg(pb + (size_t)k * LL + j1);
                s1 += u;
                if ((t11 >> k) & 1u) ct += fmaxf(u, 0.f);
                if ((t21 >> k) & 1u) wn += u;
            }
        }
    }

    // one float atomic per thread-slot; bins padded to 1 per 128B line (401 LTS slices)
    atomicAdd(&g_bins[d0 * 32], s0);
    if (has1) atomicAdd(&g_bins[d1 * 32], s1);

    // block-reduce scalars -> one float atomic each (padded lines)
    for (int o = 16; o; o >>= 1) {
        ct += __shfl_down_sync(0xffffffffu, ct, o);
        wn += __shfl_down_sync(0xffffffffu, wn, o);
    }
    __shared__ float red[2][8];
    int wid = tid >> 5, lane = tid & 31;
    if (lane == 0) { red[0][wid] = ct; red[1][wid] = wn; }
    __syncthreads();
    if (tid == 0) {
        float c = 0.f, w = 0.f;
#pragma unroll
        for (int k = 0; k < 8; ++k) { c += red[0][k]; w += red[1][k]; }
        atomicAdd(&g_scf[0],  c);
        atomicAdd(&g_scf[32], w);
    }

    // ---------- last-block finalize ----------
    __threadfence();                       // order this block's atomics device-wide
    __shared__ unsigned int rank_sh;
    if (tid == 0) rank_sh = atomicAdd(&g_done, 1u);
    __syncthreads();
    if (rank_sh != NBLK - 1) return;
    __threadfence();                       // acquire: see all other blocks' atomics

    // 256 threads: bins t0 = tid and t1 = tid + 256 (if < L)
    const int t0 = tid, t1 = tid + 256;
    const bool hb1 = (t1 < L);

    float w0_ = 0.f, ld0 = 0.f, lp0 = 0.f;
    float w1_ = 0.f, ld1 = 0.f, lp1 = 0.f;
    float v4[4] = {0.f, 0.f, 0.f, 0.f};    // n, sum(w*ld), sum(w*lp), masked-sum
    {
        float binv = g_bins[t0 * 32];
        float cntp = (t0 == 0) ? (float)L : 2.0f * (float)(L - t0);
        float mc = binv / (cntp * (float)B);
        bool valid = (t0 >= 2) && isfinite(mc) && (mc > 0.0f);
        w0_ = valid ? 1.f : 0.f;
        ld0 = logf(fmaxf((float)t0, 1.0f));
        lp0 = logf((valid ? mc : 1.0f) + 1e-6f);
        v4[0] += w0_; v4[1] += w0_ * ld0; v4[2] += w0_ * lp0;
        if (t0 >= 2) v4[3] += binv;
    }
    if (hb1) {
        float binv = g_bins[t1 * 32];
        float cntp = 2.0f * (float)(L - t1);
        float mc = binv / (cntp * (float)B);
        bool valid = isfinite(mc) && (mc > 0.0f);   // t1 >= 256 >= 2 always
        w1_ = valid ? 1.f : 0.f;
        ld1 = logf((float)t1);
        lp1 = logf((valid ? mc : 1.0f) + 1e-6f);
        v4[0] += w1_; v4[1] += w1_ * ld1; v4[2] += w1_ * lp1;
        v4[3] += binv;
    }

    // fused 4-wide block reduction (interleaved shfl chains)
    __shared__ float sc4[4][8];
    __shared__ float tot[4];
#pragma unroll
    for (int o = 16; o; o >>= 1)
#pragma unroll
        for (int q = 0; q < 4; ++q) v4[q] += __shfl_down_sync(0xffffffffu, v4[q], o);
    if (lane == 0) { sc4[0][wid] = v4[0]; sc4[1][wid] = v4[1]; sc4[2][wid] = v4[2]; sc4[3][wid] = v4[3]; }
    __syncthreads();
    if (tid < 4) {
        float s = 0.f;
#pragma unroll
        for (int k = 0; k < 8; ++k) s += sc4[tid][k];
        tot[tid] = s;
    }
    __syncthreads();

    float n  = tot[0];
    float ns = fmaxf(n, 1.0f);
    float xm = tot[1] / ns, ym = tot[2] / ns;
    float msk = tot[3];

    float v2[2];
    v2[0] = w0_ * (ld0 - xm) * (lp0 - ym) + w1_ * (ld1 - xm) * (lp1 - ym);
    v2[1] = w0_ * (ld0 - xm) * (ld0 - xm) + w1_ * (ld1 - xm) * (ld1 - xm);
#pragma unroll
    for (int o = 16; o; o >>= 1)
#pragma unroll
        for (int q = 0; q < 2; ++q) v2[q] += __shfl_down_sync(0xffffffffu, v2[q], o);
    if (lane == 0) { sc4[0][wid] = v2[0]; sc4[1][wid] = v2[1]; }
    __syncthreads();
    if (tid == 0) {
        float num = 0.f, den = 0.f;
#pragma unroll
        for (int k = 0; k < 8; ++k) { num += sc4[0][k]; den += sc4[1][k]; }

        // distance decay
        double slope = (double)num / ((double)den + 1e-8);
        double dist  = (n >= 5.0f) ? (slope + 0.85) * (slope + 0.85) : 0.0;
        // ctcf
        double ncs   = (double)g_sci[0];
        double hinge = (double)g_scf[0] / (ncs + 1e-6);
        double ctcfl = (ncs < 1.0) ? 0.0 : hinge;
        // compartment
        double cw      = (double)g_sci[32];
        double cb      = 159600.0 * (double)B - cw;   // (L-1)(L-2) masked pairs per batch
        double within  = (double)g_scf[32] / fmax(cw, 1.0);
        double between = ((double)msk - (double)g_scf[32]) / fmax(cb, 1.0);
        double ratio   = within / (fabs(between) + 1e-6);
        double compl_  = fmax(1.5 - ratio, 0.0);

        out[0] = (float)dist;
        out[1] = (float)ctcfl;
        out[2] = (float)compl_;
        out[3] = (float)(dist + 0.5 * ctcfl + 0.5 * compl_);
    }

    // ---------- reset state for next replay (this block is alone now) ----------
    __syncthreads();
    g_bins[t0 * 32] = 0.f;
    if (hb1) g_bins[t1 * 32] = 0.f;
    if (tid < 2) { g_scf[tid * 32] = 0.f; g_sci[tid * 32] = 0; }
    if (tid == 0) g_done = 0u;
}

// ---------------- launch ----------------
extern "C" void kernel_launch(void* const* d_in, const int* in_sizes, int n_in,
                              void* d_out, int out_size) {
    const float* cm     = (const float*)d_in[0];   // (B, L, L) f32
    const float* logits = (const float*)d_in[1];   // (B, L, 2) f32
    const int*   ctcf   = (const int*)d_in[2];     // (B, L)    i32
    float*       out    = (float*)d_out;           // 4 f32

    prep_kernel<<<L + B, 512>>>(ctcf, logits);
    dim3 grid(NCHUNK, L);
    main_kernel<<<grid, 256>>>(cm, out);
}